// round 1
// baseline (speedup 1.0000x reference)
#include <cuda_runtime.h>
#include <math.h>

#define N_NODES 20000
#define E_EDGES 320000
#define ET      (E_EDGES + N_NODES)   // edges + self loops = 340000
#define IN_DIM  256
#define HID     64
#define NH      4
#define C       64
#define HC      256                   // NH*C
#define DFF     128
#define NL      4

// ---------------- scratch (static device allocations; no cudaMalloc allowed) ----
__device__ float g_xh[N_NODES * HC];     // 20.5 MB
__device__ float g_as[N_NODES * NH];
__device__ float g_ad[N_NODES * NH];
__device__ float g_m [N_NODES * NH];
__device__ float g_z [N_NODES * NH];
__device__ float g_ew[ET * NH];          // 5.4 MB  exp(e - m[dst])
__device__ float g_out[N_NODES * HC];    // 20.5 MB aggregated messages
__device__ float g_ff[N_NODES * DFF];    // 10.2 MB

// ---------------- helpers ------------------------------------------------------
__device__ __forceinline__ void atomicMaxF(float* addr, float val) {
    if (val >= 0.f) atomicMax((int*)addr, __float_as_int(val));
    else            atomicMin((unsigned int*)addr, __float_as_uint(val));
}

__device__ __forceinline__ void redAddV4(float* addr, float4 v) {
    asm volatile("red.global.add.v4.f32 [%0], {%1,%2,%3,%4};"
                 :: "l"(addr), "f"(v.x), "f"(v.y), "f"(v.z), "f"(v.w) : "memory");
}

// ---------------- kernels ------------------------------------------------------

// h = (x @ We + be) * sqrt(HID);  one block (64 thr) per node
__global__ void k_embed(const float* __restrict__ x, const float* __restrict__ We,
                        const float* __restrict__ be, float* __restrict__ h) {
    __shared__ float xs[IN_DIM];
    int i = blockIdx.x;
    for (int c = threadIdx.x; c < IN_DIM; c += HID) xs[c] = x[i * IN_DIM + c];
    __syncthreads();
    int j = threadIdx.x;
    float acc = 0.f;
#pragma unroll 8
    for (int k = 0; k < IN_DIM; k++) acc = fmaf(xs[k], We[k * HID + j], acc);
    h[i * HID + j] = (acc + be[j]) * 8.0f;   // sqrt(64)
}

// xh = h @ Wc[l];  one block (256 thr) per node
__global__ void k_xh(const float* __restrict__ h, const float* __restrict__ Wc) {
    __shared__ float hs[HID];
    int i = blockIdx.x;
    if (threadIdx.x < HID) hs[threadIdx.x] = h[i * HID + threadIdx.x];
    __syncthreads();
    int j = threadIdx.x;
    float acc = 0.f;
#pragma unroll 8
    for (int k = 0; k < HID; k++) acc = fmaf(hs[k], Wc[k * HC + j], acc);
    g_xh[i * HC + j] = acc;
}

// a_s[i,h] = sum_c xh[i,h,c]*att_src;  a_d likewise. thread per (node, head)
__global__ void k_att(const float* __restrict__ att_src, const float* __restrict__ att_dst) {
    int t = blockIdx.x * blockDim.x + threadIdx.x;
    if (t >= N_NODES * NH) return;
    int i = t / NH, hh = t % NH;
    const float* row = g_xh + i * HC + hh * C;
    const float* as = att_src + hh * C;
    const float* ad = att_dst + hh * C;
    float s = 0.f, d = 0.f;
#pragma unroll 8
    for (int c = 0; c < C; c++) { float v = row[c]; s = fmaf(v, as[c], s); d = fmaf(v, ad[c], d); }
    g_as[t] = s; g_ad[t] = d;
}

// init: out = bc (broadcast), m = -inf, z = 0
__global__ void k_init(const float* __restrict__ bc) {
    int t = blockIdx.x * blockDim.x + threadIdx.x;
    if (t < N_NODES * HC) g_out[t] = bc[t & (HC - 1)];
    if (t < N_NODES * NH) { g_m[t] = -INFINITY; g_z[t] = 0.f; }
}

__device__ __forceinline__ void edge_endpoints(int e, const int* __restrict__ ei,
                                               int& src, int& dst) {
    if (e < E_EDGES) { src = ei[e]; dst = ei[E_EDGES + e]; }
    else             { src = dst = e - E_EDGES; }   // self loops appended
}

// pass 1: segment max.  thread per (edge, head)
__global__ void k_edge_max(const int* __restrict__ ei) {
    int t = blockIdx.x * blockDim.x + threadIdx.x;
    if (t >= ET * NH) return;
    int e = t / NH, hh = t % NH;
    int src, dst; edge_endpoints(e, ei, src, dst);
    float v = g_as[src * NH + hh] + g_ad[dst * NH + hh];
    v = v > 0.f ? v : 0.2f * v;                     // leaky_relu(0.2)
    atomicMaxF(&g_m[dst * NH + hh], v);
}

// pass 2: w = exp(e - m[dst]); z[dst] += w
__global__ void k_edge_exp(const int* __restrict__ ei) {
    int t = blockIdx.x * blockDim.x + threadIdx.x;
    if (t >= ET * NH) return;
    int e = t / NH, hh = t % NH;
    int src, dst; edge_endpoints(e, ei, src, dst);
    float v = g_as[src * NH + hh] + g_ad[dst * NH + hh];
    v = v > 0.f ? v : 0.2f * v;
    float w = expf(v - g_m[dst * NH + hh]);
    g_ew[t] = w;
    atomicAdd(&g_z[dst * NH + hh], w);
}

// pass 3: out[dst] += xh[src] * alpha.  one warp per edge; lane owns 8 channels.
__global__ void k_edge_aggr(const int* __restrict__ ei) {
    int w = (blockIdx.x * blockDim.x + threadIdx.x) >> 5;
    if (w >= ET) return;
    int lane = threadIdx.x & 31;
    int src, dst; edge_endpoints(w, ei, src, dst);
    float al = 0.f;
    if (lane < NH) al = g_ew[w * NH + lane] / (g_z[dst * NH + lane] + 1e-16f);
    float myal = __shfl_sync(0xffffffffu, al, lane >> 3);   // head = (lane*8)/64
    const float4* xs = (const float4*)(g_xh + src * HC);
    float4 a = xs[lane * 2], b = xs[lane * 2 + 1];
    a.x *= myal; a.y *= myal; a.z *= myal; a.w *= myal;
    b.x *= myal; b.y *= myal; b.z *= myal; b.w *= myal;
    float* op = g_out + dst * HC + lane * 8;
    redAddV4(op,     a);
    redAddV4(op + 4, b);
}

// ff = gelu(out @ W1 + b1);  one block (128 thr) per node
__global__ void k_ffn1(const float* __restrict__ W1, const float* __restrict__ b1) {
    __shared__ float os[HC];
    int i = blockIdx.x;
    for (int c = threadIdx.x; c < HC; c += DFF) os[c] = g_out[i * HC + c];
    __syncthreads();
    int j = threadIdx.x;
    float acc = 0.f;
#pragma unroll 8
    for (int k = 0; k < HC; k++) acc = fmaf(os[k], W1[k * DFF + j], acc);
    acc += b1[j];
    float g = 0.5f * acc * (1.0f + erff(acc * 0.70710678118654752f)); // exact gelu
    g_ff[i * DFF + j] = g;
}

// f = ff @ W2 + b2;  h += layernorm(f).  one block (64 thr) per node
__global__ void k_ffn2_ln(const float* __restrict__ W2, const float* __restrict__ b2,
                          const float* __restrict__ ln_g, const float* __restrict__ ln_b,
                          float* __restrict__ h) {
    __shared__ float fs[DFF];
    __shared__ float red[HID];
    int i = blockIdx.x;
    for (int c = threadIdx.x; c < DFF; c += HID) fs[c] = g_ff[i * DFF + c];
    __syncthreads();
    int j = threadIdx.x;
    float acc = 0.f;
#pragma unroll 8
    for (int k = 0; k < DFF; k++) acc = fmaf(fs[k], W2[k * HID + j], acc);
    acc += b2[j];
    red[j] = acc;
    __syncthreads();
    float sum = 0.f;
#pragma unroll 8
    for (int k = 0; k < HID; k++) sum += red[k];
    float mean = sum * (1.0f / HID);
    float var = 0.f;
#pragma unroll 8
    for (int k = 0; k < HID; k++) { float d = red[k] - mean; var = fmaf(d, d, var); }
    var *= (1.0f / HID);
    float nrm = (acc - mean) * rsqrtf(var + 1e-5f) * ln_g[j] + ln_b[j];
    h[i * HID + j] += nrm;
}

// ---------------- driver -------------------------------------------------------
extern "C" void kernel_launch(void* const* d_in, const int* in_sizes, int n_in,
                              void* d_out, int out_size) {
    const float* x       = (const float*)d_in[0];
    const int*   ei      = (const int*)  d_in[1];
    const float* We      = (const float*)d_in[2];
    const float* be      = (const float*)d_in[3];
    const float* Wc      = (const float*)d_in[4];   // [L,HID,HC]
    const float* att_src = (const float*)d_in[5];   // [L,NH,C]
    const float* att_dst = (const float*)d_in[6];
    const float* bc      = (const float*)d_in[7];   // [L,HC]
    const float* W1      = (const float*)d_in[8];   // [L,HC,DFF]
    const float* b1      = (const float*)d_in[9];   // [L,DFF]
    const float* W2      = (const float*)d_in[10];  // [L,DFF,HID]
    const float* b2      = (const float*)d_in[11];  // [L,HID]
    const float* ln_g    = (const float*)d_in[12];  // [L,HID]
    const float* ln_b    = (const float*)d_in[13];

    float* h = (float*)d_out;   // h lives in d_out, updated in place

    k_embed<<<N_NODES, HID>>>(x, We, be, h);

    const int TB = 256;
    for (int l = 0; l < NL; l++) {
        k_xh<<<N_NODES, HC>>>(h, Wc + l * HID * HC);
        k_att<<<(N_NODES * NH + TB - 1) / TB, TB>>>(att_src + l * NH * C,
                                                    att_dst + l * NH * C);
        k_init<<<(N_NODES * HC + TB - 1) / TB, TB>>>(bc + l * HC);
        k_edge_max<<<(ET * NH + TB - 1) / TB, TB>>>(ei);
        k_edge_exp<<<(ET * NH + TB - 1) / TB, TB>>>(ei);
        k_edge_aggr<<<(ET + 7) / 8, TB>>>(ei);
        k_ffn1<<<N_NODES, DFF>>>(W1 + l * HC * DFF, b1 + l * DFF);
        k_ffn2_ln<<<N_NODES, HID>>>(W2 + l * DFF * HID, b2 + l * HID,
                                    ln_g + l * HID, ln_b + l * HID, h);
    }
}

// round 3
// speedup vs baseline: 2.3614x; 2.3614x over previous
#include <cuda_runtime.h>
#include <math.h>

#define N_NODES 20000
#define E_EDGES 320000
#define ET      (E_EDGES + N_NODES)   // 340000
#define IN_DIM  256
#define HID     64
#define NH      4
#define C       64
#define HC      256
#define DFF     128
#define NL      4

// ---------------- static scratch (no cudaMalloc allowed) -----------------------
__device__ float g_xh [N_NODES * HC];    // 20.5 MB (L2-resident)
__device__ float g_as [N_NODES * NH];
__device__ float g_ad [N_NODES * NH];
__device__ float g_out[N_NODES * HC];
__device__ float g_ff [N_NODES * DFF];
__device__ int   g_off[N_NODES + 1];
__device__ int   g_cur[N_NODES];
__device__ int   g_srcl[ET];             // CSR-by-dst: src node per slot

// ================= CSR construction (graph is layer-invariant) =================
__global__ void k_csr_init() {
    int i = blockIdx.x * blockDim.x + threadIdx.x;
    if (i < N_NODES) g_cur[i] = 1;       // self loop pre-counted
}

__global__ void k_csr_count(const int* __restrict__ ei) {
    int e = blockIdx.x * blockDim.x + threadIdx.x;
    if (e < E_EDGES) atomicAdd(&g_cur[ei[E_EDGES + e]], 1);
}

// one block, 1024 threads: exclusive prefix of g_cur -> g_off, reset cursors
__global__ void k_csr_scan() {
    __shared__ int ps[1024];
    const int CH = 20;                   // 1024*20 >= 20000
    int t = threadIdx.x;
    int base = t * CH;
    int mysum = 0;
    for (int i = 0; i < CH; i++) { int idx = base + i; if (idx < N_NODES) mysum += g_cur[idx]; }
    ps[t] = mysum;
    __syncthreads();
    for (int d = 1; d < 1024; d <<= 1) {
        int v = (t >= d) ? ps[t - d] : 0;
        __syncthreads();
        ps[t] += v;
        __syncthreads();
    }
    int run = ps[t] - mysum;             // exclusive
    for (int i = 0; i < CH; i++) {
        int idx = base + i;
        if (idx < N_NODES) { int deg = g_cur[idx]; g_off[idx] = run; g_cur[idx] = run; run += deg; }
    }
    if (t == 1023) g_off[N_NODES] = ps[1023];
}

__global__ void k_csr_fill(const int* __restrict__ ei) {
    int e = blockIdx.x * blockDim.x + threadIdx.x;
    if (e >= ET) return;
    int src, dst;
    if (e < E_EDGES) { src = ei[e]; dst = ei[E_EDGES + e]; }
    else             { src = dst = e - E_EDGES; }
    int pos = atomicAdd(&g_cur[dst], 1);
    g_srcl[pos] = src;
}

// ================= dense kernels (register-tiled, weight-in-regs) ==============

// h = (x @ We + be) * 8.  block 256 = 64 cols x 4 node-groups; 40 nodes/block
__global__ void k_embed(const float* __restrict__ x, const float* __restrict__ We,
                        const float* __restrict__ be, float* __restrict__ h) {
    int t = threadIdx.x;
    int j = t & 63, g = t >> 6;
    int n0 = blockIdx.x * 40;
    __shared__ __align__(16) float4 xs[40 * 16];
    float acc[10];
#pragma unroll
    for (int n = 0; n < 10; n++) acc[n] = 0.f;
#pragma unroll 1
    for (int kc = 0; kc < 4; kc++) {
        float w[64];
#pragma unroll
        for (int k = 0; k < 64; k++) w[k] = We[(size_t)(kc * 64 + k) * HID + j];
        __syncthreads();
        for (int fi = t; fi < 640; fi += 256) {
            int row = fi >> 4, c4 = fi & 15;
            xs[fi] = *(const float4*)(x + (size_t)(n0 + row) * IN_DIM + kc * 64 + c4 * 4);
        }
        __syncthreads();
#pragma unroll
        for (int k4 = 0; k4 < 16; k4++) {
#pragma unroll
            for (int n = 0; n < 10; n++) {
                float4 f = xs[(g * 10 + n) * 16 + k4];
                acc[n] = fmaf(w[k4 * 4 + 0], f.x, acc[n]);
                acc[n] = fmaf(w[k4 * 4 + 1], f.y, acc[n]);
                acc[n] = fmaf(w[k4 * 4 + 2], f.z, acc[n]);
                acc[n] = fmaf(w[k4 * 4 + 3], f.w, acc[n]);
            }
        }
    }
    float bj = be[j];
#pragma unroll
    for (int n = 0; n < 10; n++)
        h[(size_t)(n0 + g * 10 + n) * HID + j] = (acc[n] + bj) * 8.0f;
}

// xh = h @ Wc.  block 256 cols; 40 nodes/block in 5 groups of 8
__global__ void k_xh(const float* __restrict__ h, const float* __restrict__ Wc) {
    int j = threadIdx.x;
    int n0 = blockIdx.x * 40;
    float w[64];
#pragma unroll
    for (int k = 0; k < 64; k++) w[k] = Wc[(size_t)k * HC + j];
    __shared__ __align__(16) float4 xs[8 * 16];
#pragma unroll 1
    for (int grp = 0; grp < 5; grp++) {
        int base = n0 + grp * 8;
        __syncthreads();
        if (j < 128) xs[j] = *((const float4*)(h + (size_t)base * HID) + j);
        __syncthreads();
        float acc[8];
#pragma unroll
        for (int r = 0; r < 8; r++) acc[r] = 0.f;
#pragma unroll
        for (int k4 = 0; k4 < 16; k4++) {
#pragma unroll
            for (int r = 0; r < 8; r++) {
                float4 f = xs[r * 16 + k4];
                acc[r] = fmaf(w[k4 * 4 + 0], f.x, acc[r]);
                acc[r] = fmaf(w[k4 * 4 + 1], f.y, acc[r]);
                acc[r] = fmaf(w[k4 * 4 + 2], f.z, acc[r]);
                acc[r] = fmaf(w[k4 * 4 + 3], f.w, acc[r]);
            }
        }
#pragma unroll
        for (int r = 0; r < 8; r++) g_xh[(size_t)(base + r) * HC + j] = acc[r];
    }
}

// a_s, a_d per (node, head)
__global__ void k_att(const float* __restrict__ att_src, const float* __restrict__ att_dst) {
    int t = blockIdx.x * blockDim.x + threadIdx.x;
    if (t >= N_NODES * NH) return;
    int i = t >> 2, hh = t & 3;
    const float4* row = (const float4*)(g_xh + (size_t)i * HC + hh * C);
    const float4* as  = (const float4*)(att_src + hh * C);
    const float4* ad  = (const float4*)(att_dst + hh * C);
    float s = 0.f, d = 0.f;
#pragma unroll
    for (int c = 0; c < 16; c++) {
        float4 v = row[c], A = as[c], D = ad[c];
        s = fmaf(v.x, A.x, s); s = fmaf(v.y, A.y, s); s = fmaf(v.z, A.z, s); s = fmaf(v.w, A.w, s);
        d = fmaf(v.x, D.x, d); d = fmaf(v.y, D.y, d); d = fmaf(v.z, D.z, d); d = fmaf(v.w, D.w, d);
    }
    g_as[t] = s; g_ad[t] = d;
}

// GAT aggregation: one warp per dst node, CSR edge list, no atomics.
__global__ void k_gat(const float* __restrict__ bc) {
    int w = (blockIdx.x * blockDim.x + threadIdx.x) >> 5;
    if (w >= N_NODES) return;
    int lane = threadIdx.x & 31;
    int hh = lane >> 3;                         // head owning channels [lane*8, lane*8+8)
    int beg = g_off[w], end = g_off[w + 1];
    float ad = g_ad[w * NH + hh];
    float m = -INFINITY;
    for (int p = beg; p < end; p++) {
        int s = g_srcl[p];
        float e = g_as[s * NH + hh] + ad;
        e = e > 0.f ? e : 0.2f * e;
        m = fmaxf(m, e);
    }
    float z = 0.f;
    float a0 = 0, a1 = 0, a2 = 0, a3 = 0, a4 = 0, a5 = 0, a6 = 0, a7 = 0;
    for (int p = beg; p < end; p++) {
        int s = g_srcl[p];
        float e = g_as[s * NH + hh] + ad;
        e = e > 0.f ? e : 0.2f * e;
        float wg = __expf(e - m);
        z += wg;
        const float4* xr = (const float4*)(g_xh + (size_t)s * HC + lane * 8);
        float4 a = xr[0], b = xr[1];
        a0 = fmaf(wg, a.x, a0); a1 = fmaf(wg, a.y, a1); a2 = fmaf(wg, a.z, a2); a3 = fmaf(wg, a.w, a3);
        a4 = fmaf(wg, b.x, a4); a5 = fmaf(wg, b.y, a5); a6 = fmaf(wg, b.z, a6); a7 = fmaf(wg, b.w, a7);
    }
    float inv = 1.f / (z + 1e-16f);
    const float4* bcv = (const float4*)(bc + lane * 8);
    float4 c0 = bcv[0], c1 = bcv[1];
    float4 o0 = make_float4(fmaf(a0, inv, c0.x), fmaf(a1, inv, c0.y), fmaf(a2, inv, c0.z), fmaf(a3, inv, c0.w));
    float4 o1 = make_float4(fmaf(a4, inv, c1.x), fmaf(a5, inv, c1.y), fmaf(a6, inv, c1.z), fmaf(a7, inv, c1.w));
    float4* op = (float4*)(g_out + (size_t)w * HC + lane * 8);
    op[0] = o0; op[1] = o1;
}

// ff = gelu(out @ W1 + b1).  block 128 cols; 16 nodes/block
__global__ void k_ffn1(const float* __restrict__ W1, const float* __restrict__ b1) {
    int j = threadIdx.x;
    int n0 = blockIdx.x * 16;
    float acc[16];
#pragma unroll
    for (int n = 0; n < 16; n++) acc[n] = 0.f;
    __shared__ __align__(16) float4 xs[16 * 16];
#pragma unroll 1
    for (int kc = 0; kc < 4; kc++) {
        float w[64];
#pragma unroll
        for (int k = 0; k < 64; k++) w[k] = W1[(size_t)(kc * 64 + k) * DFF + j];
        __syncthreads();
        for (int fi = j; fi < 256; fi += 128) {
            int row = fi >> 4, c4 = fi & 15;
            xs[fi] = *(const float4*)(g_out + (size_t)(n0 + row) * HC + kc * 64 + c4 * 4);
        }
        __syncthreads();
#pragma unroll
        for (int k4 = 0; k4 < 16; k4++) {
#pragma unroll
            for (int n = 0; n < 16; n++) {
                float4 f = xs[n * 16 + k4];
                acc[n] = fmaf(w[k4 * 4 + 0], f.x, acc[n]);
                acc[n] = fmaf(w[k4 * 4 + 1], f.y, acc[n]);
                acc[n] = fmaf(w[k4 * 4 + 2], f.z, acc[n]);
                acc[n] = fmaf(w[k4 * 4 + 3], f.w, acc[n]);
            }
        }
    }
    float bj = b1[j];
#pragma unroll
    for (int n = 0; n < 16; n++) {
        float v = acc[n] + bj;
        g_ff[(size_t)(n0 + n) * DFF + j] = 0.5f * v * (1.0f + erff(v * 0.70710678118654752f));
    }
}

// f = ff @ W2 + b2;  h += layernorm(f).  block 64 cols; 16 nodes/block
__global__ void k_ffn2_ln(const float* __restrict__ W2, const float* __restrict__ b2,
                          const float* __restrict__ lng, const float* __restrict__ lnb,
                          float* __restrict__ h) {
    int j = threadIdx.x;                        // 0..63
    int n0 = blockIdx.x * 16;
    float acc[16];
#pragma unroll
    for (int n = 0; n < 16; n++) acc[n] = 0.f;
    __shared__ __align__(16) float sbuf[16 * 65];   // GEMM tile view + padded LN view
    __shared__ float2 stats[16];
    float4* xs = (float4*)sbuf;                 // 16 rows x 16 float4 (stride 64 floats)
#pragma unroll 1
    for (int kc = 0; kc < 2; kc++) {
        float w[64];
#pragma unroll
        for (int k = 0; k < 64; k++) w[k] = W2[(size_t)(kc * 64 + k) * HID + j];
        __syncthreads();
        for (int fi = j; fi < 256; fi += 64) {
            int row = fi >> 4, c4 = fi & 15;
            xs[fi] = *(const float4*)(g_ff + (size_t)(n0 + row) * DFF + kc * 64 + c4 * 4);
        }
        __syncthreads();
#pragma unroll
        for (int k4 = 0; k4 < 16; k4++) {
#pragma unroll
            for (int n = 0; n < 16; n++) {
                float4 f = xs[n * 16 + k4];
                acc[n] = fmaf(w[k4 * 4 + 0], f.x, acc[n]);
                acc[n] = fmaf(w[k4 * 4 + 1], f.y, acc[n]);
                acc[n] = fmaf(w[k4 * 4 + 2], f.z, acc[n]);
                acc[n] = fmaf(w[k4 * 4 + 3], f.w, acc[n]);
            }
        }
    }
    float bj = b2[j];
#pragma unroll
    for (int n = 0; n < 16; n++) acc[n] += bj;
    // LN stats: padded-stride stash, 4 threads per node
    __syncthreads();
#pragma unroll
    for (int n = 0; n < 16; n++) sbuf[n * 65 + j] = acc[n];
    __syncthreads();
    int node = j >> 2, part = j & 3;
    float s = 0.f, sq = 0.f;
#pragma unroll
    for (int k = 0; k < 16; k++) {
        float v = sbuf[node * 65 + part * 16 + k];
        s += v; sq = fmaf(v, v, sq);
    }
    s  += __shfl_xor_sync(0xffffffffu, s, 1);  s  += __shfl_xor_sync(0xffffffffu, s, 2);
    sq += __shfl_xor_sync(0xffffffffu, sq, 1); sq += __shfl_xor_sync(0xffffffffu, sq, 2);
    if (part == 0) {
        float mean = s * (1.f / 64.f);
        stats[node] = make_float2(mean, sq * (1.f / 64.f) - mean * mean);
    }
    __syncthreads();
    float gj = lng[j], lbj = lnb[j];
#pragma unroll
    for (int n = 0; n < 16; n++) {
        float2 st = stats[n];
        float nv = (acc[n] - st.x) * rsqrtf(st.y + 1e-5f) * gj + lbj;
        h[(size_t)(n0 + n) * HID + j] += nv;
    }
}

// ================= driver ======================================================
extern "C" void kernel_launch(void* const* d_in, const int* in_sizes, int n_in,
                              void* d_out, int out_size) {
    const float* x       = (const float*)d_in[0];
    const int*   ei      = (const int*)  d_in[1];
    const float* We      = (const float*)d_in[2];
    const float* be      = (const float*)d_in[3];
    const float* Wc      = (const float*)d_in[4];
    const float* att_src = (const float*)d_in[5];
    const float* att_dst = (const float*)d_in[6];
    const float* bc      = (const float*)d_in[7];
    const float* W1      = (const float*)d_in[8];
    const float* b1      = (const float*)d_in[9];
    const float* W2      = (const float*)d_in[10];
    const float* b2      = (const float*)d_in[11];
    const float* ln_g    = (const float*)d_in[12];
    const float* ln_b    = (const float*)d_in[13];

    float* h = (float*)d_out;

    // CSR by dst (layer-invariant)
    k_csr_init <<<(N_NODES + 255) / 256, 256>>>();
    k_csr_count<<<(E_EDGES + 255) / 256, 256>>>(ei);
    k_csr_scan <<<1, 1024>>>();
    k_csr_fill <<<(ET + 255) / 256, 256>>>(ei);

    k_embed<<<500, 256>>>(x, We, be, h);

    for (int l = 0; l < NL; l++) {
        k_xh     <<<500, 256>>>(h, Wc + (size_t)l * HID * HC);
        k_att    <<<(N_NODES * NH + 255) / 256, 256>>>(att_src + l * NH * C, att_dst + l * NH * C);
        k_gat    <<<2500, 256>>>(bc + l * HC);
        k_ffn1   <<<1250, 128>>>(W1 + (size_t)l * HC * DFF, b1 + l * DFF);
        k_ffn2_ln<<<1250, 64>>> (W2 + (size_t)l * DFF * HID, b2 + l * HID,
                                 ln_g + l * HID, ln_b + l * HID, h);
    }
}

// round 4
// speedup vs baseline: 2.6239x; 1.1112x over previous
#include <cuda_runtime.h>
#include <cuda_fp16.h>
#include <math.h>

#define N_NODES 20000
#define E_EDGES 320000
#define ET      (E_EDGES + N_NODES)   // 340000
#define IN_DIM  256
#define HID     64
#define NH      4
#define C       64
#define HC      256
#define DFF     128
#define NL      4

// ---------------- static scratch (no cudaMalloc allowed) -----------------------
__device__ __half g_xh_h[N_NODES * HC];  // 10.2 MB fp16 messages (L2-resident)
__device__ float  g_as [N_NODES * NH];
__device__ float  g_ad [N_NODES * NH];
__device__ float  g_out[N_NODES * HC];
__device__ int    g_off[N_NODES + 1];
__device__ int    g_cur[N_NODES];
__device__ int    g_srcl[ET];            // CSR-by-dst: src node per slot

// ================= CSR construction (graph is layer-invariant) =================
__global__ void k_csr_init() {
    int i = blockIdx.x * blockDim.x + threadIdx.x;
    if (i < N_NODES) g_cur[i] = 1;       // self loop pre-counted
}

__global__ void k_csr_count(const int* __restrict__ ei) {
    int e = blockIdx.x * blockDim.x + threadIdx.x;
    if (e < E_EDGES) atomicAdd(&g_cur[ei[E_EDGES + e]], 1);
}

__global__ void k_csr_scan() {
    __shared__ int ps[1024];
    const int CH = 20;
    int t = threadIdx.x;
    int base = t * CH;
    int mysum = 0;
    for (int i = 0; i < CH; i++) { int idx = base + i; if (idx < N_NODES) mysum += g_cur[idx]; }
    ps[t] = mysum;
    __syncthreads();
    for (int d = 1; d < 1024; d <<= 1) {
        int v = (t >= d) ? ps[t - d] : 0;
        __syncthreads();
        ps[t] += v;
        __syncthreads();
    }
    int run = ps[t] - mysum;
    for (int i = 0; i < CH; i++) {
        int idx = base + i;
        if (idx < N_NODES) { int deg = g_cur[idx]; g_off[idx] = run; g_cur[idx] = run; run += deg; }
    }
    if (t == 1023) g_off[N_NODES] = ps[1023];
}

__global__ void k_csr_fill(const int* __restrict__ ei) {
    int e = blockIdx.x * blockDim.x + threadIdx.x;
    if (e >= ET) return;
    int src, dst;
    if (e < E_EDGES) { src = ei[e]; dst = ei[E_EDGES + e]; }
    else             { src = dst = e - E_EDGES; }
    int pos = atomicAdd(&g_cur[dst], 1);
    g_srcl[pos] = src;
}

// ================= dense kernels ==============================================

// h = (x @ We + be) * 8.  block 256 = 64 cols x 4 groups; 40 nodes/block
__global__ void k_embed(const float* __restrict__ x, const float* __restrict__ We,
                        const float* __restrict__ be, float* __restrict__ h) {
    int t = threadIdx.x;
    int j = t & 63, g = t >> 6;
    int n0 = blockIdx.x * 40;
    __shared__ __align__(16) float4 xs[40 * 16];
    float acc[10];
#pragma unroll
    for (int n = 0; n < 10; n++) acc[n] = 0.f;
#pragma unroll 1
    for (int kc = 0; kc < 4; kc++) {
        float w[64];
#pragma unroll
        for (int k = 0; k < 64; k++) w[k] = We[(size_t)(kc * 64 + k) * HID + j];
        __syncthreads();
        for (int fi = t; fi < 640; fi += 256) {
            int row = fi >> 4, c4 = fi & 15;
            xs[fi] = *(const float4*)(x + (size_t)(n0 + row) * IN_DIM + kc * 64 + c4 * 4);
        }
        __syncthreads();
#pragma unroll
        for (int k4 = 0; k4 < 16; k4++) {
#pragma unroll
            for (int n = 0; n < 10; n++) {
                float4 f = xs[(g * 10 + n) * 16 + k4];
                acc[n] = fmaf(w[k4 * 4 + 0], f.x, acc[n]);
                acc[n] = fmaf(w[k4 * 4 + 1], f.y, acc[n]);
                acc[n] = fmaf(w[k4 * 4 + 2], f.z, acc[n]);
                acc[n] = fmaf(w[k4 * 4 + 3], f.w, acc[n]);
            }
        }
    }
    float bj = be[j];
#pragma unroll
    for (int n = 0; n < 10; n++)
        h[(size_t)(n0 + g * 10 + n) * HID + j] = (acc[n] + bj) * 8.0f;
}

// xh = h @ Wc (fp16 out) fused with a_s/a_d reduction.  block 256; 40 nodes/block
__global__ void k_xh_att(const float* __restrict__ h, const float* __restrict__ Wc,
                         const float* __restrict__ att_src, const float* __restrict__ att_dst) {
    int j = threadIdx.x;                 // output channel 0..255
    int wid = j >> 5, lane = j & 31;
    int n0 = blockIdx.x * 40;
    float w[64];
#pragma unroll
    for (int k = 0; k < 64; k++) w[k] = Wc[(size_t)k * HC + j];
    float asj = att_src[j], adj = att_dst[j];
    __shared__ __align__(16) float4 xs[8 * 16];
    __shared__ float s_part[8][8], d_part[8][8];   // [warp][row]
#pragma unroll 1
    for (int grp = 0; grp < 5; grp++) {
        int base = n0 + grp * 8;
        __syncthreads();
        if (j < 128) xs[j] = *((const float4*)(h + (size_t)base * HID) + j);
        __syncthreads();
        float acc[8];
#pragma unroll
        for (int r = 0; r < 8; r++) acc[r] = 0.f;
#pragma unroll
        for (int k4 = 0; k4 < 16; k4++) {
#pragma unroll
            for (int r = 0; r < 8; r++) {
                float4 f = xs[r * 16 + k4];
                acc[r] = fmaf(w[k4 * 4 + 0], f.x, acc[r]);
                acc[r] = fmaf(w[k4 * 4 + 1], f.y, acc[r]);
                acc[r] = fmaf(w[k4 * 4 + 2], f.z, acc[r]);
                acc[r] = fmaf(w[k4 * 4 + 3], f.w, acc[r]);
            }
        }
#pragma unroll
        for (int r = 0; r < 8; r++)
            g_xh_h[(size_t)(base + r) * HC + j] = __float2half_rn(acc[r]);
        // attention partials: warp-reduce acc*att over the 32 channels of this warp
#pragma unroll
        for (int r = 0; r < 8; r++) {
            float sv = acc[r] * asj, dv = acc[r] * adj;
#pragma unroll
            for (int o = 16; o; o >>= 1) {
                sv += __shfl_xor_sync(0xffffffffu, sv, o);
                dv += __shfl_xor_sync(0xffffffffu, dv, o);
            }
            if (lane == 0) { s_part[wid][r] = sv; d_part[wid][r] = dv; }
        }
        __syncthreads();
        if (j < 32) {                    // r = j>>2, head = j&3; head spans warps 2h,2h+1
            int r = j >> 2, hh = j & 3;
            g_as[(size_t)(base + r) * NH + hh] = s_part[hh * 2][r] + s_part[hh * 2 + 1][r];
            g_ad[(size_t)(base + r) * NH + hh] = d_part[hh * 2][r] + d_part[hh * 2 + 1][r];
        }
    }
}

// GAT aggregation: one warp per dst node, fp16 gather, no atomics.
__global__ void k_gat(const float* __restrict__ bc) {
    int w = (blockIdx.x * blockDim.x + threadIdx.x) >> 5;
    if (w >= N_NODES) return;
    int lane = threadIdx.x & 31;
    int hh = lane >> 3;                  // head owning channels [lane*8, lane*8+8)
    int beg = g_off[w], end = g_off[w + 1];
    float ad = g_ad[w * NH + hh];
    float m = -INFINITY;
    for (int p = beg; p < end; p++) {
        int s = g_srcl[p];
        float e = g_as[s * NH + hh] + ad;
        e = e > 0.f ? e : 0.2f * e;
        m = fmaxf(m, e);
    }
    float z = 0.f;
    float a0 = 0, a1 = 0, a2 = 0, a3 = 0, a4 = 0, a5 = 0, a6 = 0, a7 = 0;
    for (int p = beg; p < end; p++) {
        int s = g_srcl[p];
        float e = g_as[s * NH + hh] + ad;
        e = e > 0.f ? e : 0.2f * e;
        float wg = __expf(e - m);
        z += wg;
        uint4 v = *(const uint4*)(g_xh_h + (size_t)s * HC + lane * 8);  // 8 halves
        const __half2* hp = (const __half2*)&v;
        float2 f0 = __half22float2(hp[0]), f1 = __half22float2(hp[1]);
        float2 f2 = __half22float2(hp[2]), f3 = __half22float2(hp[3]);
        a0 = fmaf(wg, f0.x, a0); a1 = fmaf(wg, f0.y, a1);
        a2 = fmaf(wg, f1.x, a2); a3 = fmaf(wg, f1.y, a3);
        a4 = fmaf(wg, f2.x, a4); a5 = fmaf(wg, f2.y, a5);
        a6 = fmaf(wg, f3.x, a6); a7 = fmaf(wg, f3.y, a7);
    }
    float inv = 1.f / (z + 1e-16f);
    const float4* bcv = (const float4*)(bc + lane * 8);
    float4 c0 = bcv[0], c1 = bcv[1];
    float4 o0 = make_float4(fmaf(a0, inv, c0.x), fmaf(a1, inv, c0.y), fmaf(a2, inv, c0.z), fmaf(a3, inv, c0.w));
    float4 o1 = make_float4(fmaf(a4, inv, c1.x), fmaf(a5, inv, c1.y), fmaf(a6, inv, c1.z), fmaf(a7, inv, c1.w));
    float4* op = (float4*)(g_out + (size_t)w * HC + lane * 8);
    op[0] = o0; op[1] = o1;
}

// fused FFN: f = gelu(out@W1+b1)@W2 + b2;  h += layernorm(f).  128 thr; 16 nodes
__global__ void k_ffn(const float* __restrict__ W1, const float* __restrict__ b1,
                      const float* __restrict__ W2, const float* __restrict__ b2,
                      const float* __restrict__ lng, const float* __restrict__ lnb,
                      float* __restrict__ h) {
    int j = threadIdx.x;                 // 0..127
    int n0 = blockIdx.x * 16;
    __shared__ __align__(16) float4 xs[16 * 16];  // 4 KB input tile
    __shared__ __align__(16) float sff[16 * 128]; // 8 KB ff tile (reused for LN stash)
    __shared__ float2 stats[16];
    // ---- stage A: ff = gelu(out @ W1 + b1), thread = DFF column j ----
    float acc[16];
#pragma unroll
    for (int n = 0; n < 16; n++) acc[n] = 0.f;
#pragma unroll 1
    for (int kc = 0; kc < 4; kc++) {
        float w[64];
#pragma unroll
        for (int k = 0; k < 64; k++) w[k] = W1[(size_t)(kc * 64 + k) * DFF + j];
        __syncthreads();
        for (int fi = j; fi < 256; fi += 128) {
            int row = fi >> 4, c4 = fi & 15;
            xs[fi] = *(const float4*)(g_out + (size_t)(n0 + row) * HC + kc * 64 + c4 * 4);
        }
        __syncthreads();
#pragma unroll
        for (int k4 = 0; k4 < 16; k4++) {
#pragma unroll
            for (int n = 0; n < 16; n++) {
                float4 f = xs[n * 16 + k4];
                acc[n] = fmaf(w[k4 * 4 + 0], f.x, acc[n]);
                acc[n] = fmaf(w[k4 * 4 + 1], f.y, acc[n]);
                acc[n] = fmaf(w[k4 * 4 + 2], f.z, acc[n]);
                acc[n] = fmaf(w[k4 * 4 + 3], f.w, acc[n]);
            }
        }
    }
    {
        float bj = b1[j];
#pragma unroll
        for (int n = 0; n < 16; n++) {
            float v = acc[n] + bj;
            sff[n * 128 + j] = 0.5f * v * (1.0f + erff(v * 0.70710678118654752f));
        }
    }
    __syncthreads();
    // ---- stage B: f = ff @ W2 + b2;  thread = (group g of 8 nodes, HID col j2) ----
    int j2 = j & 63, g = j >> 6;
    float acc2[8];
#pragma unroll
    for (int r = 0; r < 8; r++) acc2[r] = 0.f;
#pragma unroll 1
    for (int kc = 0; kc < 2; kc++) {
        float w[64];
#pragma unroll
        for (int k = 0; k < 64; k++) w[k] = W2[(size_t)(kc * 64 + k) * HID + j2];
#pragma unroll
        for (int k4 = 0; k4 < 16; k4++) {
#pragma unroll
            for (int r = 0; r < 8; r++) {
                float4 f = *(const float4*)&sff[(g * 8 + r) * 128 + kc * 64 + k4 * 4];
                acc2[r] = fmaf(w[k4 * 4 + 0], f.x, acc2[r]);
                acc2[r] = fmaf(w[k4 * 4 + 1], f.y, acc2[r]);
                acc2[r] = fmaf(w[k4 * 4 + 2], f.z, acc2[r]);
                acc2[r] = fmaf(w[k4 * 4 + 3], f.w, acc2[r]);
            }
        }
    }
    {
        float bj = b2[j2];
#pragma unroll
        for (int r = 0; r < 8; r++) acc2[r] += bj;
    }
    // ---- LayerNorm over HID=64 per node ----
    __syncthreads();                     // all sff reads done; safe to reuse
    float* sln = sff;                    // stride-65 padded stash
#pragma unroll
    for (int r = 0; r < 8; r++) sln[(g * 8 + r) * 65 + j2] = acc2[r];
    __syncthreads();
    int node = j >> 3, part = j & 7;     // 8 threads per node
    float s = 0.f, sq = 0.f;
#pragma unroll
    for (int k = 0; k < 8; k++) {
        float v = sln[node * 65 + part * 8 + k];
        s += v; sq = fmaf(v, v, sq);
    }
    s  += __shfl_xor_sync(0xffffffffu, s, 1);  s  += __shfl_xor_sync(0xffffffffu, s, 2);  s  += __shfl_xor_sync(0xffffffffu, s, 4);
    sq += __shfl_xor_sync(0xffffffffu, sq, 1); sq += __shfl_xor_sync(0xffffffffu, sq, 2); sq += __shfl_xor_sync(0xffffffffu, sq, 4);
    if (part == 0) {
        float mean = s * (1.f / 64.f);
        stats[node] = make_float2(mean, sq * (1.f / 64.f) - mean * mean);
    }
    __syncthreads();
    float gj = lng[j2], lbj = lnb[j2];
#pragma unroll
    for (int r = 0; r < 8; r++) {
        int nd = g * 8 + r;
        float2 st = stats[nd];
        float nv = (acc2[r] - st.x) * rsqrtf(st.y + 1e-5f) * gj + lbj;
        h[(size_t)(n0 + nd) * HID + j2] += nv;
    }
}

// ================= driver ======================================================
extern "C" void kernel_launch(void* const* d_in, const int* in_sizes, int n_in,
                              void* d_out, int out_size) {
    const float* x       = (const float*)d_in[0];
    const int*   ei      = (const int*)  d_in[1];
    const float* We      = (const float*)d_in[2];
    const float* be      = (const float*)d_in[3];
    const float* Wc      = (const float*)d_in[4];
    const float* att_src = (const float*)d_in[5];
    const float* att_dst = (const float*)d_in[6];
    const float* bc      = (const float*)d_in[7];
    const float* W1      = (const float*)d_in[8];
    const float* b1      = (const float*)d_in[9];
    const float* W2      = (const float*)d_in[10];
    const float* b2      = (const float*)d_in[11];
    const float* ln_g    = (const float*)d_in[12];
    const float* ln_b    = (const float*)d_in[13];

    float* h = (float*)d_out;

    k_csr_init <<<(N_NODES + 255) / 256, 256>>>();
    k_csr_count<<<(E_EDGES + 255) / 256, 256>>>(ei);
    k_csr_scan <<<1, 1024>>>();
    k_csr_fill <<<(ET + 255) / 256, 256>>>(ei);

    k_embed<<<500, 256>>>(x, We, be, h);

    for (int l = 0; l < NL; l++) {
        k_xh_att<<<500, 256>>>(h, Wc + (size_t)l * HID * HC,
                               att_src + l * NH * C, att_dst + l * NH * C);
        k_gat   <<<2500, 256>>>(bc + l * HC);
        k_ffn   <<<1250, 128>>>(W1 + (size_t)l * HC * DFF, b1 + l * DFF,
                                W2 + (size_t)l * DFF * HID, b2 + l * HID,
                                ln_g + l * HID, ln_b + l * HID, h);
    }
}

// round 5
// speedup vs baseline: 2.7116x; 1.0334x over previous
#include <cuda_runtime.h>
#include <cuda_fp16.h>
#include <math.h>

#define N_NODES 20000
#define E_EDGES 320000
#define ET      (E_EDGES + N_NODES)   // 340000
#define IN_DIM  256
#define HID     64
#define NH      4
#define C       64
#define HC      256
#define DFF     128
#define NL      4

typedef unsigned long long u64t;

// packed f32x2 helpers (FFMA2 path — ptxas never emits it from C++)
#define FMA2(d, a, b) asm("fma.rn.f32x2 %0, %1, %2, %0;" : "+l"(d) : "l"(a), "l"(b))
__device__ __forceinline__ u64t pk2(float lo, float hi) {
    u64t r; asm("mov.b64 %0, {%1, %2};" : "=l"(r) : "f"(lo), "f"(hi)); return r;
}
__device__ __forceinline__ float2 upk2(u64t v) {
    float2 f; asm("mov.b64 {%0, %1}, %2;" : "=f"(f.x), "=f"(f.y) : "l"(v)); return f;
}

// ---------------- static scratch (no cudaMalloc allowed) -----------------------
__device__ __half g_xh_h[N_NODES * HC];  // 10.2 MB fp16 messages (L2-resident)
__device__ float  g_as [N_NODES * NH];
__device__ float  g_ad [N_NODES * NH];
__device__ float  g_out[N_NODES * HC];
__device__ int    g_off[N_NODES + 1];
__device__ int    g_cur[N_NODES];
__device__ int    g_srcl[ET];            // CSR-by-dst: src node per slot

// ================= CSR construction (graph is layer-invariant) =================
__global__ void k_csr_init() {
    int i = blockIdx.x * blockDim.x + threadIdx.x;
    if (i < N_NODES) g_cur[i] = 1;       // self loop pre-counted
}

__global__ void k_csr_count(const int* __restrict__ ei) {
    int e = blockIdx.x * blockDim.x + threadIdx.x;
    if (e < E_EDGES) atomicAdd(&g_cur[ei[E_EDGES + e]], 1);
}

__global__ void k_csr_scan() {
    __shared__ int ps[1024];
    const int CH = 20;
    int t = threadIdx.x;
    int base = t * CH;
    int mysum = 0;
    for (int i = 0; i < CH; i++) { int idx = base + i; if (idx < N_NODES) mysum += g_cur[idx]; }
    ps[t] = mysum;
    __syncthreads();
    for (int d = 1; d < 1024; d <<= 1) {
        int v = (t >= d) ? ps[t - d] : 0;
        __syncthreads();
        ps[t] += v;
        __syncthreads();
    }
    int run = ps[t] - mysum;
    for (int i = 0; i < CH; i++) {
        int idx = base + i;
        if (idx < N_NODES) { int deg = g_cur[idx]; g_off[idx] = run; g_cur[idx] = run; run += deg; }
    }
    if (t == 1023) g_off[N_NODES] = ps[1023];
}

__global__ void k_csr_fill(const int* __restrict__ ei) {
    int e = blockIdx.x * blockDim.x + threadIdx.x;
    if (e >= ET) return;
    int src, dst;
    if (e < E_EDGES) { src = ei[e]; dst = ei[E_EDGES + e]; }
    else             { src = dst = e - E_EDGES; }
    int pos = atomicAdd(&g_cur[dst], 1);
    g_srcl[pos] = src;
}

// ================= dense kernels (FFMA2 k-paired) ==============================

// h = (x @ We + be) * 8.  block 256 = 64 cols x 4 groups; 40 nodes/block
__global__ void k_embed(const float* __restrict__ x, const float* __restrict__ We,
                        const float* __restrict__ be, float* __restrict__ h) {
    int t = threadIdx.x;
    int j = t & 63, g = t >> 6;
    int n0 = blockIdx.x * 40;
    __shared__ __align__(16) float4 xs[40 * 16];
    u64t accp[10];
#pragma unroll
    for (int n = 0; n < 10; n++) accp[n] = 0ULL;
#pragma unroll 1
    for (int kc = 0; kc < 4; kc++) {
        u64t wp[32];
#pragma unroll
        for (int m = 0; m < 32; m++)
            wp[m] = pk2(We[(size_t)(kc * 64 + 2 * m) * HID + j],
                        We[(size_t)(kc * 64 + 2 * m + 1) * HID + j]);
        __syncthreads();
        for (int fi = t; fi < 640; fi += 256) {
            int row = fi >> 4, c4 = fi & 15;
            xs[fi] = *(const float4*)(x + (size_t)(n0 + row) * IN_DIM + kc * 64 + c4 * 4);
        }
        __syncthreads();
#pragma unroll
        for (int k4 = 0; k4 < 16; k4++) {
#pragma unroll
            for (int n = 0; n < 10; n++) {
                ulonglong2 v = ((const ulonglong2*)xs)[(g * 10 + n) * 16 + k4];
                FMA2(accp[n], wp[2 * k4],     v.x);
                FMA2(accp[n], wp[2 * k4 + 1], v.y);
            }
        }
    }
    float bj = be[j];
#pragma unroll
    for (int n = 0; n < 10; n++) {
        float2 f = upk2(accp[n]);
        h[(size_t)(n0 + g * 10 + n) * HID + j] = (f.x + f.y + bj) * 8.0f;
    }
}

// xh = h @ Wc (fp16 out) fused with a_s/a_d reduction.  block 256; 40 nodes/block
__global__ void k_xh_att(const float* __restrict__ h, const float* __restrict__ Wc,
                         const float* __restrict__ att_src, const float* __restrict__ att_dst) {
    int j = threadIdx.x;                 // output channel 0..255
    int wid = j >> 5, lane = j & 31;
    int n0 = blockIdx.x * 40;
    u64t wp[32];
#pragma unroll
    for (int m = 0; m < 32; m++)
        wp[m] = pk2(Wc[(size_t)(2 * m) * HC + j], Wc[(size_t)(2 * m + 1) * HC + j]);
    float asj = att_src[j], adj = att_dst[j];
    __shared__ __align__(16) float4 xs[8 * 16];
    __shared__ float s_part[8][8], d_part[8][8];   // [warp][row]
#pragma unroll 1
    for (int grp = 0; grp < 5; grp++) {
        int base = n0 + grp * 8;
        __syncthreads();
        if (j < 128) xs[j] = *((const float4*)(h + (size_t)base * HID) + j);
        __syncthreads();
        u64t accp[8];
#pragma unroll
        for (int r = 0; r < 8; r++) accp[r] = 0ULL;
#pragma unroll
        for (int k4 = 0; k4 < 16; k4++) {
#pragma unroll
            for (int r = 0; r < 8; r++) {
                ulonglong2 v = ((const ulonglong2*)xs)[r * 16 + k4];
                FMA2(accp[r], wp[2 * k4],     v.x);
                FMA2(accp[r], wp[2 * k4 + 1], v.y);
            }
        }
        float acc[8];
#pragma unroll
        for (int r = 0; r < 8; r++) { float2 f = upk2(accp[r]); acc[r] = f.x + f.y; }
#pragma unroll
        for (int r = 0; r < 8; r++)
            g_xh_h[(size_t)(base + r) * HC + j] = __float2half_rn(acc[r]);
        // attention partials: warp-reduce acc*att over the 32 channels of this warp
#pragma unroll
        for (int r = 0; r < 8; r++) {
            float sv = acc[r] * asj, dv = acc[r] * adj;
#pragma unroll
            for (int o = 16; o; o >>= 1) {
                sv += __shfl_xor_sync(0xffffffffu, sv, o);
                dv += __shfl_xor_sync(0xffffffffu, dv, o);
            }
            if (lane == 0) { s_part[wid][r] = sv; d_part[wid][r] = dv; }
        }
        __syncthreads();
        if (j < 32) {                    // r = j>>2, head = j&3; head spans warps 2h,2h+1
            int r = j >> 2, hh = j & 3;
            g_as[(size_t)(base + r) * NH + hh] = s_part[hh * 2][r] + s_part[hh * 2 + 1][r];
            g_ad[(size_t)(base + r) * NH + hh] = d_part[hh * 2][r] + d_part[hh * 2 + 1][r];
        }
    }
}

// GAT aggregation: one warp per dst node, single-pass online softmax, no atomics.
__global__ void k_gat(const float* __restrict__ bc) {
    int w = (blockIdx.x * blockDim.x + threadIdx.x) >> 5;
    if (w >= N_NODES) return;
    int lane = threadIdx.x & 31;
    int hh = lane >> 3;                  // head owning channels [lane*8, lane*8+8)
    int beg = g_off[w], end = g_off[w + 1];
    float ad = g_ad[w * NH + hh];
    float m = -INFINITY, z = 0.f;
    float a0 = 0, a1 = 0, a2 = 0, a3 = 0, a4 = 0, a5 = 0, a6 = 0, a7 = 0;
    for (int p = beg; p < end; p++) {
        int s = g_srcl[p];
        float e = g_as[s * NH + hh] + ad;
        e = e > 0.f ? e : 0.2f * e;
        if (e > m) {                     // rare rescale (online softmax)
            float corr = __expf(m - e); // first iter: exp(-inf)=0 zeroes state
            m = e;
            z *= corr;
            a0 *= corr; a1 *= corr; a2 *= corr; a3 *= corr;
            a4 *= corr; a5 *= corr; a6 *= corr; a7 *= corr;
        }
        float wg = __expf(e - m);
        z += wg;
        uint4 v = *(const uint4*)(g_xh_h + (size_t)s * HC + lane * 8);  // 8 halves
        const __half2* hp = (const __half2*)&v;
        float2 f0 = __half22float2(hp[0]), f1 = __half22float2(hp[1]);
        float2 f2 = __half22float2(hp[2]), f3 = __half22float2(hp[3]);
        a0 = fmaf(wg, f0.x, a0); a1 = fmaf(wg, f0.y, a1);
        a2 = fmaf(wg, f1.x, a2); a3 = fmaf(wg, f1.y, a3);
        a4 = fmaf(wg, f2.x, a4); a5 = fmaf(wg, f2.y, a5);
        a6 = fmaf(wg, f3.x, a6); a7 = fmaf(wg, f3.y, a7);
    }
    float inv = 1.f / (z + 1e-16f);
    const float4* bcv = (const float4*)(bc + lane * 8);
    float4 c0 = bcv[0], c1 = bcv[1];
    float4 o0 = make_float4(fmaf(a0, inv, c0.x), fmaf(a1, inv, c0.y), fmaf(a2, inv, c0.z), fmaf(a3, inv, c0.w));
    float4 o1 = make_float4(fmaf(a4, inv, c1.x), fmaf(a5, inv, c1.y), fmaf(a6, inv, c1.z), fmaf(a7, inv, c1.w));
    float4* op = (float4*)(g_out + (size_t)w * HC + lane * 8);
    op[0] = o0; op[1] = o1;
}

// fused FFN: f = gelu(out@W1+b1)@W2 + b2;  h += layernorm(f).  128 thr; 16 nodes
__global__ void k_ffn(const float* __restrict__ W1, const float* __restrict__ b1,
                      const float* __restrict__ W2, const float* __restrict__ b2,
                      const float* __restrict__ lng, const float* __restrict__ lnb,
                      float* __restrict__ h) {
    int j = threadIdx.x;                 // 0..127
    int n0 = blockIdx.x * 16;
    __shared__ __align__(16) float4 xs[16 * 16];  // 4 KB input tile
    __shared__ __align__(16) float sff[16 * 128]; // 8 KB ff tile (reused for LN stash)
    __shared__ float2 stats[16];
    // ---- stage A: ff = gelu(out @ W1 + b1), thread = DFF column j ----
    u64t accp[16];
#pragma unroll
    for (int n = 0; n < 16; n++) accp[n] = 0ULL;
#pragma unroll 1
    for (int kc = 0; kc < 4; kc++) {
        u64t wp[32];
#pragma unroll
        for (int m = 0; m < 32; m++)
            wp[m] = pk2(W1[(size_t)(kc * 64 + 2 * m) * DFF + j],
                        W1[(size_t)(kc * 64 + 2 * m + 1) * DFF + j]);
        __syncthreads();
        for (int fi = j; fi < 256; fi += 128) {
            int row = fi >> 4, c4 = fi & 15;
            xs[fi] = *(const float4*)(g_out + (size_t)(n0 + row) * HC + kc * 64 + c4 * 4);
        }
        __syncthreads();
#pragma unroll
        for (int k4 = 0; k4 < 16; k4++) {
#pragma unroll
            for (int n = 0; n < 16; n++) {
                ulonglong2 v = ((const ulonglong2*)xs)[n * 16 + k4];
                FMA2(accp[n], wp[2 * k4],     v.x);
                FMA2(accp[n], wp[2 * k4 + 1], v.y);
            }
        }
    }
    {
        float bj = b1[j];
#pragma unroll
        for (int n = 0; n < 16; n++) {
            float2 f = upk2(accp[n]);
            float v = f.x + f.y + bj;
            sff[n * 128 + j] = 0.5f * v * (1.0f + erff(v * 0.70710678118654752f));
        }
    }
    __syncthreads();
    // ---- stage B: f = ff @ W2 + b2;  thread = (group g of 8 nodes, HID col j2) ----
    int j2 = j & 63, g = j >> 6;
    u64t accp2[8];
#pragma unroll
    for (int r = 0; r < 8; r++) accp2[r] = 0ULL;
#pragma unroll 1
    for (int kc = 0; kc < 2; kc++) {
        u64t wp[32];
#pragma unroll
        for (int m = 0; m < 32; m++)
            wp[m] = pk2(W2[(size_t)(kc * 64 + 2 * m) * HID + j2],
                        W2[(size_t)(kc * 64 + 2 * m + 1) * HID + j2]);
#pragma unroll
        for (int k4 = 0; k4 < 16; k4++) {
#pragma unroll
            for (int r = 0; r < 8; r++) {
                ulonglong2 v = *(const ulonglong2*)&sff[(g * 8 + r) * 128 + kc * 64 + k4 * 4];
                FMA2(accp2[r], wp[2 * k4],     v.x);
                FMA2(accp2[r], wp[2 * k4 + 1], v.y);
            }
        }
    }
    float acc2[8];
    {
        float bj = b2[j2];
#pragma unroll
        for (int r = 0; r < 8; r++) { float2 f = upk2(accp2[r]); acc2[r] = f.x + f.y + bj; }
    }
    // ---- LayerNorm over HID=64 per node ----
    __syncthreads();                     // all sff reads done; safe to reuse
    float* sln = sff;                    // stride-65 padded stash
#pragma unroll
    for (int r = 0; r < 8; r++) sln[(g * 8 + r) * 65 + j2] = acc2[r];
    __syncthreads();
    int node = j >> 3, part = j & 7;     // 8 threads per node
    float s = 0.f, sq = 0.f;
#pragma unroll
    for (int k = 0; k < 8; k++) {
        float v = sln[node * 65 + part * 8 + k];
        s += v; sq = fmaf(v, v, sq);
    }
    s  += __shfl_xor_sync(0xffffffffu, s, 1);  s  += __shfl_xor_sync(0xffffffffu, s, 2);  s  += __shfl_xor_sync(0xffffffffu, s, 4);
    sq += __shfl_xor_sync(0xffffffffu, sq, 1); sq += __shfl_xor_sync(0xffffffffu, sq, 2); sq += __shfl_xor_sync(0xffffffffu, sq, 4);
    if (part == 0) {
        float mean = s * (1.f / 64.f);
        stats[node] = make_float2(mean, sq * (1.f / 64.f) - mean * mean);
    }
    __syncthreads();
    float gj = lng[j2], lbj = lnb[j2];
#pragma unroll
    for (int r = 0; r < 8; r++) {
        int nd = g * 8 + r;
        float2 st = stats[nd];
        float nv = (acc2[r] - st.x) * rsqrtf(st.y + 1e-5f) * gj + lbj;
        h[(size_t)(n0 + nd) * HID + j2] += nv;
    }
}

// ================= driver ======================================================
extern "C" void kernel_launch(void* const* d_in, const int* in_sizes, int n_in,
                              void* d_out, int out_size) {
    const float* x       = (const float*)d_in[0];
    const int*   ei      = (const int*)  d_in[1];
    const float* We      = (const float*)d_in[2];
    const float* be      = (const float*)d_in[3];
    const float* Wc      = (const float*)d_in[4];
    const float* att_src = (const float*)d_in[5];
    const float* att_dst = (const float*)d_in[6];
    const float* bc      = (const float*)d_in[7];
    const float* W1      = (const float*)d_in[8];
    const float* b1      = (const float*)d_in[9];
    const float* W2      = (const float*)d_in[10];
    const float* b2      = (const float*)d_in[11];
    const float* ln_g    = (const float*)d_in[12];
    const float* ln_b    = (const float*)d_in[13];

    float* h = (float*)d_out;

    k_csr_init <<<(N_NODES + 255) / 256, 256>>>();
    k_csr_count<<<(E_EDGES + 255) / 256, 256>>>(ei);
    k_csr_scan <<<1, 1024>>>();
    k_csr_fill <<<(ET + 255) / 256, 256>>>(ei);

    k_embed<<<500, 256>>>(x, We, be, h);

    for (int l = 0; l < NL; l++) {
        k_xh_att<<<500, 256>>>(h, Wc + (size_t)l * HID * HC,
                               att_src + l * NH * C, att_dst + l * NH * C);
        k_gat   <<<2500, 256>>>(bc + l * HC);
        k_ffn   <<<1250, 128>>>(W1 + (size_t)l * HC * DFF, b1 + l * DFF,
                                W2 + (size_t)l * DFF * HID, b2 + l * HID,
                                ln_g + l * HID, ln_b + l * HID, h);
    }
}